// round 15
// baseline (speedup 1.0000x reference)
#include <cuda_runtime.h>
#include <math.h>

#define Nn 20000
#define Ee 320000
#define ET (Ee + Nn)
#define Bb 128
#define IN_F 25
#define D 64
#define HD 8
#define HDD (HD * D) /* 512 */
#define TCAP 256     /* s2s shared tile capacity (rows) */

// ---------------- scratch (static device globals; no allocation) ----------------
__device__ float g_h0[Nn * D];          // 5.1 MB (L2-resident)
__device__ float g_as[Nn * HD];
__device__ float g_ad[Nn * HD];
__device__ float g_cs[HD * D];
__device__ float g_cd[HD * D];
__device__ int   g_cnt[Nn];
__device__ int   g_off[Nn + 1];
__device__ int   g_cur[Nn];
__device__ int   g_esrc[ET];
__device__ float g_outF[Nn * D];        // 5.1 MB
__device__ int   g_gstart[Bb];
__device__ int   g_gcnt[Bb];
__device__ float g_w2[Nn];
__device__ int   g_is64;
__device__ int   g_bsum[32];
__device__ int   g_bflag[32];

__device__ __forceinline__ float sigf(float x) { return 1.0f / (1.0f + __expf(-x)); }

// ---- packed fp32x2 helpers ----
__device__ __forceinline__ unsigned long long pk2(float lo, float hi) {
    unsigned long long r;
    asm("mov.b64 %0, {%1,%2};" : "=l"(r) : "f"(lo), "f"(hi));
    return r;
}
__device__ __forceinline__ void upk2(unsigned long long v, float& lo, float& hi) {
    asm("mov.b64 {%0,%1}, %2;" : "=f"(lo), "=f"(hi) : "l"(v));
}
__device__ __forceinline__ void fma2(unsigned long long& acc, unsigned long long a,
                                     unsigned long long b) {
    asm("fma.rn.f32x2 %0, %1, %2, %0;" : "+l"(acc) : "l"(a), "l"(b));
}

// ---------------- fused prologue: detect dtype + init + c_s/c_d -----------------
__global__ void k_pre(const void* __restrict__ ei, const float* __restrict__ Wg,
                      const float* __restrict__ att_src, const float* __restrict__ att_dst) {
    int i = blockIdx.x * blockDim.x + threadIdx.x;
    if (i == 0) {
        const int2* p = (const int2*)ei;
        int ok64 = 1;
        for (int j = 0; j < 64; j++) if (p[j].y != 0) ok64 = 0;
        g_is64 = ok64;
    }
    if (i < Nn) g_cnt[i] = 0;
    if (i < Bb) { g_gstart[i] = Nn; g_gcnt[i] = 0; }
    if (i < 32) { g_bflag[i] = 0; g_bsum[i] = 0; }
    int w = i >> 5, lane = i & 31;
    int k = w >> 4, h = (w >> 1) & 7, side = w & 1;
    const float* att = side ? att_dst : att_src;
    float2 wv = *(const float2*)(Wg + (size_t)k * HDD + h * D + 2 * lane);
    float2 av = *(const float2*)(att + h * D + 2 * lane);
    float s = wv.x * av.x + wv.y * av.y;
#pragma unroll
    for (int o = 16; o > 0; o >>= 1) s += __shfl_xor_sync(0xffffffff, s, o);
    if (lane == 0) {
        if (side) g_cd[h * D + k] = s;
        else      g_cs[h * D + k] = s;
    }
}

// ---------------- dst histogram + graph segments --------------------------------
__global__ void k_hist(const void* __restrict__ ei, const void* __restrict__ bat) {
    int i = blockIdx.x * blockDim.x + threadIdx.x;
    int is64 = g_is64;
    if (i < Ee) {
        int d = is64 ? (int)((const long long*)ei)[Ee + i] : ((const int*)ei)[Ee + i];
        atomicAdd(&g_cnt[d], 1);
    }
    if (i < Nn) {
        int b = is64 ? (int)((const long long*)bat)[i] : ((const int*)bat)[i];
        atomicMin(&g_gstart[b], i);
        atomicAdd(&g_gcnt[b], 1);
        atomicAdd(&g_cnt[i], 1);                        // self-loop
    }
}

// ---------------- h0 = relu(x@W0+b0);  a_s/a_d = h0 . c_s/c_d -------------------
__global__ void k_h0att(const float* __restrict__ x, const float* __restrict__ W0,
                        const float* __restrict__ b0) {
    __shared__ float sx[16 * IN_F];
    __shared__ float sW[IN_F * D];
    __shared__ float sh[16][65];
    int tid = threadIdx.x;  // 256
    int r0 = blockIdx.x * 16;
    for (int i = tid; i < 16 * IN_F; i += 256) sx[i] = x[r0 * IN_F + i];
    for (int i = tid; i < IN_F * D; i += 256) sW[i] = W0[i];
    __syncthreads();
    for (int i = tid; i < 1024; i += 256) {
        int r = i >> 6, c = i & 63;
        float a = b0[c];
#pragma unroll
        for (int k = 0; k < IN_F; k++) a = fmaf(sx[r * IN_F + k], sW[k * D + c], a);
        sh[r][c] = fmaxf(a, 0.f);
    }
    __syncthreads();
    {
        int r = tid >> 4, q = tid & 15;
        float4 v = make_float4(sh[r][q * 4], sh[r][q * 4 + 1], sh[r][q * 4 + 2], sh[r][q * 4 + 3]);
        *(float4*)(g_h0 + (size_t)(r0 + r) * D + q * 4) = v;
    }
    {
        int r = tid >> 4, hs = tid & 15, h = hs >> 1;
        const float* cv = (hs & 1) ? g_cd : g_cs;
        float a = 0.f;
#pragma unroll 8
        for (int k = 0; k < D; k++) a = fmaf(sh[r][k], cv[h * D + k], a);
        if (hs & 1) g_ad[(r0 + r) * HD + h] = a;
        else        g_as[(r0 + r) * HD + h] = a;
    }
}

// ---------------- decoupled-lookback scan: grid 20 x 1024 -----------------------
__global__ void k_scan() {
    __shared__ int ws[32];
    __shared__ int s_base;
    int b = blockIdx.x, tid = threadIdx.x;
    int idx = b * 1000 + tid;
    int v = (tid < 1000) ? g_cnt[idx] : 0;
    int lane = tid & 31, wid = tid >> 5;
    int sc = v;
#pragma unroll
    for (int o = 1; o < 32; o <<= 1) {
        int t = __shfl_up_sync(0xffffffff, sc, o);
        if (lane >= o) sc += t;
    }
    if (lane == 31) ws[wid] = sc;
    __syncthreads();
    if (wid == 0) {
        int s = ws[lane];
#pragma unroll
        for (int o = 1; o < 32; o <<= 1) {
            int t = __shfl_up_sync(0xffffffff, s, o);
            if (lane >= o) s += t;
        }
        ws[lane] = s;
    }
    __syncthreads();
    int incl = sc + (wid ? ws[wid - 1] : 0);
    if (tid == 0) {
        g_bsum[b] = ws[31];
        __threadfence();
        atomicExch(&g_bflag[b], 1);
    }
    if (wid == 0) {
        int contrib = 0;
        if (lane < b) {
            while (atomicAdd(&g_bflag[lane], 0) == 0) {}
            contrib = atomicAdd(&g_bsum[lane], 0);
        }
#pragma unroll
        for (int o = 16; o > 0; o >>= 1) contrib += __shfl_xor_sync(0xffffffff, contrib, o);
        if (lane == 0) s_base = contrib;
    }
    __syncthreads();
    int ex = s_base + incl - v;
    if (tid < 1000) {
        g_off[idx] = ex;
        g_cur[idx] = ex;
    }
    if (b == 19 && tid == 999) g_off[Nn] = s_base + incl;
}

// ---------------- scatter (reads edge_index directly) ---------------------------
__global__ void k_scatter(const void* __restrict__ ei) {
    int e = blockIdx.x * blockDim.x + threadIdx.x;
    if (e >= ET) return;
    int src, dst;
    if (e < Ee) {
        if (g_is64) {
            src = (int)((const long long*)ei)[e];
            dst = (int)((const long long*)ei)[Ee + e];
        } else {
            src = ((const int*)ei)[e];
            dst = ((const int*)ei)[Ee + e];
        }
    } else { src = e - Ee; dst = src; }
    int p = atomicAdd(&g_cur[dst], 1);
    g_esrc[p] = src;
}

// ---------------- MEGA-FUSED: softmax-agg -> per-head GEMM -> dense GEMM --------
// 512 threads, 16 dst nodes per block. Aggregation results go straight into the
// transposed shared tile sp[k][r] (pitch 20) that the GEMM phases consume; the
// 41MB g_p tensor and its round trip are gone.
__global__ void k_aggbig(const float* __restrict__ Wg, const float* __restrict__ bg,
                         const float* __restrict__ Wh, const float* __restrict__ bh) {
    __shared__ __align__(16) float sp[512 * 20];  // 40 KB
    int tid = threadIdx.x;  // 512
    int w = tid >> 5, lane = tid & 31;
    int r0 = blockIdx.x * 16;
    // ---- phase 0: per-dst segment softmax + h0 aggregation (warp w -> node r0+w)
    {
        int v = r0 + w;
        int beg = g_off[v], end = g_off[v + 1];
        float adh = (lane < 8) ? g_ad[v * HD + lane] : 0.f;
        float ssum = 0.f;
        float2 acc[8];
#pragma unroll
        for (int h = 0; h < 8; h++) acc[h] = make_float2(0.f, 0.f);
        for (int i = beg; i < end; i++) {
            int s = g_esrc[i];
            float wgt = 0.f;
            if (lane < 8) {
                float e = g_as[s * HD + lane] + adh;
                e = (e > 0.f) ? e : 0.2f * e;
                wgt = __expf(e);
                ssum += wgt;
            }
            float2 hp = *((const float2*)(g_h0 + (size_t)s * D) + lane);
#pragma unroll
            for (int h = 0; h < 8; h++) {
                float wh = __shfl_sync(0xffffffff, wgt, h);
                acc[h].x = fmaf(wh, hp.x, acc[h].x);
                acc[h].y = fmaf(wh, hp.y, acc[h].y);
            }
        }
        float invl = (lane < 8) ? 1.f / ssum : 0.f;
#pragma unroll
        for (int h = 0; h < 8; h++) {
            float iv = __shfl_sync(0xffffffff, invl, h);
            sp[(h * D + 2 * lane) * 20 + w]     = acc[h].x * iv;
            sp[(h * D + 2 * lane + 1) * 20 + w] = acc[h].y * iv;
        }
    }
    __syncthreads();
    // ---- phase 1: per-head 64x64 GEMM; thread owns global col c = tid
    {
        int c = tid;
        int hb = (c >> 6) << 6;
        unsigned long long a1[8];
#pragma unroll
        for (int q = 0; q < 8; q++) a1[q] = 0ULL;
#pragma unroll 2
        for (int kk = 0; kk < 64; kk++) {
            float wv = Wg[(size_t)kk * HDD + c];
            unsigned long long wp = pk2(wv, wv);
            const ulonglong2* row = (const ulonglong2*)(sp + (hb + kk) * 20);
#pragma unroll
            for (int q = 0; q < 4; q++) {
                ulonglong2 av = row[q];
                fma2(a1[2 * q], av.x, wp);
                fma2(a1[2 * q + 1], av.y, wp);
            }
        }
        float bgc = bg[c];
        __syncthreads();  // all reads of p-tile done
#pragma unroll
        for (int q = 0; q < 8; q++) {
            float f0, f1;
            upk2(a1[q], f0, f1);
            *(float2*)(sp + c * 20 + 2 * q) =
                make_float2(fmaxf(f0 + bgc, 0.f), fmaxf(f1 + bgc, 0.f));
        }
    }
    __syncthreads();
    // ---- phase 2: dense 512 -> 64; thread = (col c2, row pair 2*rg, 2*rg+1)
    {
        int c2 = tid & 63, rg = tid >> 6;  // rg 0..7
        unsigned long long b0 = 0ULL, b1 = 0ULL;
#pragma unroll 4
        for (int j = 0; j < 512; j += 2) {
            float wv = Wh[(size_t)j * D + c2];
            unsigned long long wp = pk2(wv, wv);
            unsigned long long av = *(const unsigned long long*)(sp + j * 20 + 2 * rg);
            fma2(b0, av, wp);
            float wv2 = Wh[(size_t)(j + 1) * D + c2];
            unsigned long long wp2 = pk2(wv2, wv2);
            unsigned long long av2 = *(const unsigned long long*)(sp + (j + 1) * 20 + 2 * rg);
            fma2(b1, av2, wp2);
        }
        float bhc = bh[c2];
        float f0, f1, g0, g1;
        upk2(b0, f0, f1);
        upk2(b1, g0, g1);
        size_t ob = (size_t)(r0 + 2 * rg) * D + c2;
        g_outF[ob]     = fmaxf(f0 + g0 + bhc, 0.f);
        g_outF[ob + D] = fmaxf(f1 + g1 + bhc, 0.f);
    }
}

// ---------------- fully fused Set2Set (3 iters) + final MLP ---------------------
__global__ void k_s2s(const float* __restrict__ W_ih, const float* __restrict__ W_hh,
                      const float* __restrict__ b_ih, const float* __restrict__ b_hh,
                      const float* __restrict__ W1, const float* __restrict__ b1,
                      const float* __restrict__ W2, const float* __restrict__ b2,
                      float* __restrict__ out) {
    extern __shared__ __align__(16) float st[];   // TCAP * 64
    __shared__ __align__(16) float sqs[2 * D];
    __shared__ __align__(16) float shh[D], scc[D], sq[D], sg[4 * D];
    __shared__ float se[TCAP];
    __shared__ float red[256];
    int b = blockIdx.x, tid = threadIdx.x;  // 256
    if (tid < 2 * D) sqs[tid] = 0.f;
    if (tid < D) { shh[tid] = 0.f; scc[tid] = 0.f; }
    int start = g_gstart[b], cnt = g_gcnt[b];
    bool fast = (cnt <= TCAP);
    const float* baseF;
    float* sw;
    if (fast) {
        const float4* gsrc = (const float4*)(g_outF + (size_t)start * D);
        float4* gdst = (float4*)st;
        for (int i = tid; i < cnt * 16; i += 256) gdst[i] = gsrc[i];
        baseF = st;
        sw = se;
    } else {
        baseF = g_outF + (size_t)start * D;
        sw = g_w2 + start;
    }
    __syncthreads();
    for (int it = 0; it < 3; it++) {
        float acc = b_ih[tid] + b_hh[tid];
        const float4* wi = (const float4*)(W_ih + tid * 2 * D);
#pragma unroll
        for (int k = 0; k < 2 * D / 4; k++) {
            float4 w = wi[k];
            acc += w.x * sqs[4 * k] + w.y * sqs[4 * k + 1] + w.z * sqs[4 * k + 2] + w.w * sqs[4 * k + 3];
        }
        const float4* wh = (const float4*)(W_hh + tid * D);
#pragma unroll
        for (int k = 0; k < D / 4; k++) {
            float4 w = wh[k];
            acc += w.x * shh[4 * k] + w.y * shh[4 * k + 1] + w.z * shh[4 * k + 2] + w.w * shh[4 * k + 3];
        }
        sg[tid] = acc;
        __syncthreads();
        if (tid < D) {
            float ig = sg[tid], fg = sg[D + tid], gg = sg[2 * D + tid], og = sg[3 * D + tid];
            float c = sigf(fg) * scc[tid] + sigf(ig) * tanhf(gg);
            float hv = sigf(og) * tanhf(c);
            scc[tid] = c; shh[tid] = hv; sq[tid] = hv;
        }
        __syncthreads();
        float lm = -3.0e38f;
        const float4* q4 = (const float4*)sq;
        for (int i = tid; i < cnt; i += 256) {
            const float4* orow = (const float4*)(baseF + (size_t)i * D);
            float e = 0.f;
#pragma unroll
            for (int j = 0; j < 16; j++) {
                float4 o = orow[j], qv = q4[j];
                e += o.x * qv.x + o.y * qv.y + o.z * qv.z + o.w * qv.w;
            }
            sw[i] = e;
            lm = fmaxf(lm, e);
        }
        red[tid] = lm;
        __syncthreads();
        for (int o = 128; o > 0; o >>= 1) {
            if (tid < o) red[tid] = fmaxf(red[tid], red[tid + o]);
            __syncthreads();
        }
        float m2 = red[0];
        __syncthreads();
        float ls = 0.f;
        for (int i = tid; i < cnt; i += 256) {
            float w = __expf(sw[i] - m2);
            sw[i] = w;
            ls += w;
        }
        red[tid] = ls;
        __syncthreads();
        for (int o = 128; o > 0; o >>= 1) {
            if (tid < o) red[tid] += red[tid + o];
            __syncthreads();
        }
        float s2 = red[0];
        __syncthreads();
        int c = tid & 63, g = tid >> 6;
        float racc = 0.f;
        for (int i = g; i < cnt; i += 4)
            racc += sw[i] * baseF[(size_t)i * D + c];
        red[tid] = racc;
        __syncthreads();
        if (tid < 64) {
            float r = red[tid] + red[64 + tid] + red[128 + tid] + red[192 + tid];
            sqs[D + tid] = (cnt > 0) ? r / s2 : 0.f;
            sqs[tid] = sq[tid];
        }
        __syncthreads();
    }
    if (tid < D) {
        float acc = b1[tid];
        for (int k = 0; k < 2 * D; k++) acc = fmaf(sqs[k], W1[k * D + tid], acc);
        red[tid] = fmaxf(acc, 0.f) * W2[tid];
    }
    __syncthreads();
    if (tid < 32) red[tid] += red[tid + 32];
    __syncthreads();
    if (tid < 16) red[tid] += red[tid + 16];
    __syncthreads();
    if (tid < 8) red[tid] += red[tid + 8];
    __syncthreads();
    if (tid < 4) red[tid] += red[tid + 4];
    __syncthreads();
    if (tid < 2) red[tid] += red[tid + 2];
    __syncthreads();
    if (tid == 0) out[b] = red[0] + red[1] + b2[0];
}

// ---------------- launch --------------------------------------------------------
extern "C" void kernel_launch(void* const* d_in, const int* in_sizes, int n_in,
                              void* d_out, int out_size) {
    const float* x        = (const float*)d_in[0];
    const void*  ei       = d_in[1];
    const void*  bat      = d_in[2];
    const float* W0       = (const float*)d_in[3];
    const float* b0       = (const float*)d_in[4];
    const float* Wg       = (const float*)d_in[5];
    const float* att_src  = (const float*)d_in[6];
    const float* att_dst  = (const float*)d_in[7];
    const float* bg       = (const float*)d_in[8];
    const float* Wh       = (const float*)d_in[9];
    const float* bh       = (const float*)d_in[10];
    const float* W_ih     = (const float*)d_in[11];
    const float* W_hh     = (const float*)d_in[12];
    const float* b_ih     = (const float*)d_in[13];
    const float* b_hh     = (const float*)d_in[14];
    const float* W1       = (const float*)d_in[15];
    const float* b1       = (const float*)d_in[16];
    const float* W2       = (const float*)d_in[17];
    const float* b2       = (const float*)d_in[18];
    float* out            = (float*)d_out;

    cudaFuncSetAttribute(k_s2s, cudaFuncAttributeMaxDynamicSharedMemorySize,
                         TCAP * D * (int)sizeof(float));

    k_pre<<<128, 256>>>(ei, Wg, att_src, att_dst);
    k_hist<<<(Ee + 255) / 256, 256>>>(ei, bat);
    k_h0att<<<Nn / 16, 256>>>(x, W0, b0);
    k_scan<<<20, 1024>>>();
    k_scatter<<<(ET + 255) / 256, 256>>>(ei);
    k_aggbig<<<Nn / 16, 512>>>(Wg, bg, Wh, bh);
    k_s2s<<<Bb, 256, TCAP * D * (int)sizeof(float)>>>(W_ih, W_hh, b_ih, b_hh,
                                                      W1, b1, W2, b2, out);
}